// round 5
// baseline (speedup 1.0000x reference)
#include <cuda_runtime.h>
#include <cuda_bf16.h>
#include <cstdint>
#include <math.h>

#define Bc   8
#define Hh   8
#define Dd   512
#define HD   64
#define LNS  64
#define LS   2048
#define LSO  512
#define LQ   (LSO + LNS)   // 576
#define LK   (LS + LNS)    // 2112
#define LL   (LS + LNS)
#define DELTA (LK - LQ)    // 1536

__device__ float g_Q[(size_t)Bc * Hh * LQ * HD];
__device__ float g_K[(size_t)Bc * Hh * LK * HD];
__device__ float g_V[(size_t)Bc * Hh * LK * HD];
__device__ float g_attn[(size_t)Bc * LQ * Dd];

// ---------------------------------------------------------------------------
// helpers
// ---------------------------------------------------------------------------
__device__ __forceinline__ void mma8(float* c, const unsigned* a, const unsigned* b) {
    asm volatile(
        "mma.sync.aligned.m16n8k8.row.col.f32.tf32.tf32.f32 "
        "{%0,%1,%2,%3},{%4,%5,%6,%7},{%8,%9},{%0,%1,%2,%3};\n"
        : "+f"(c[0]), "+f"(c[1]), "+f"(c[2]), "+f"(c[3])
        : "r"(a[0]), "r"(a[1]), "r"(a[2]), "r"(a[3]), "r"(b[0]), "r"(b[1]));
}

__device__ __forceinline__ void mma16bf(float* c, const unsigned* a, const unsigned* b) {
    asm volatile(
        "mma.sync.aligned.m16n8k16.row.col.f32.bf16.bf16.f32 "
        "{%0,%1,%2,%3},{%4,%5,%6,%7},{%8,%9},{%0,%1,%2,%3};\n"
        : "+f"(c[0]), "+f"(c[1]), "+f"(c[2]), "+f"(c[3])
        : "r"(a[0]), "r"(a[1]), "r"(a[2]), "r"(a[3]), "r"(b[0]), "r"(b[1]));
}

__device__ __forceinline__ unsigned pack_bf2(float f0, float f1) {
    unsigned r;
    asm("cvt.rn.bf16x2.f32 %0, %1, %2;" : "=r"(r) : "f"(f1), "f"(f0));
    return r;
}

__device__ __forceinline__ void cp16(uint32_t sdst, const void* gsrc) {
    asm volatile("cp.async.ca.shared.global [%0], [%1], 16;\n" :: "r"(sdst), "l"(gsrc));
}
__device__ __forceinline__ void cp_commit() {
    asm volatile("cp.async.commit_group;\n" ::: "memory");
}
__device__ __forceinline__ void cp_wait0() {
    asm volatile("cp.async.wait_group 0;\n" ::: "memory");
}

// ---------------------------------------------------------------------------
// Split-bf16 GEMM. z selects (W, bias, Out) pair (K/V fusion).
// ---------------------------------------------------------------------------
__global__ __launch_bounds__(256) void gemm_tc(
    const float* __restrict__ X,
    const float* __restrict__ W0, const float* __restrict__ bias0, float* __restrict__ Out0,
    const float* __restrict__ W1, const float* __restrict__ bias1, float* __restrict__ Out1,
    int bt, int tok_off, int Lx, int mode, int Lout, int out_tok_off)
{
    const float* W    = (blockIdx.z == 0) ? W0    : W1;
    const float* bias = (blockIdx.z == 0) ? bias0 : bias1;
    float*       Out  = (blockIdx.z == 0) ? Out0  : Out1;

    __shared__ unsigned Ah[16][136], Al[16][136];
    __shared__ unsigned Bh[16][72],  Bl[16][72];

    const int tid  = threadIdx.x;
    const int lane = tid & 31, warp = tid >> 5;
    const int wm = warp >> 1, wn = warp & 1;
    const int g  = lane >> 2, tg = lane & 3;
    const int m0 = blockIdx.y << 7, n0 = blockIdx.x << 6;

    const int am = tid & 127;
    const int ak = (tid >> 7) << 4;
    const int gm = m0 + am;
    const float* xrow = X + ((size_t)(gm / bt) * Lx + tok_off + (gm % bt)) * (size_t)Dd;

    const int kp = tid >> 4;
    const int n4 = (tid & 15) << 2;
    const float* wptr = W + (size_t)(2 * kp) * Dd + n0 + n4;

    float acc[2][4][4];
    #pragma unroll
    for (int a = 0; a < 2; a++)
        #pragma unroll
        for (int b = 0; b < 4; b++)
            #pragma unroll
            for (int c = 0; c < 4; c++) acc[a][b][c] = 0.f;

    for (int k0 = 0; k0 < Dd; k0 += 32) {
        #pragma unroll
        for (int v = 0; v < 4; v++) {
            float4 x4 = *(const float4*)(xrow + k0 + ak + v * 4);
            unsigned h0 = pack_bf2(x4.x, x4.y);
            unsigned h1 = pack_bf2(x4.z, x4.w);
            float l0x = x4.x - __uint_as_float(h0 << 16);
            float l0y = x4.y - __uint_as_float(h0 & 0xffff0000u);
            float l1z = x4.z - __uint_as_float(h1 << 16);
            float l1w = x4.w - __uint_as_float(h1 & 0xffff0000u);
            const int k2 = (ak >> 1) + v * 2;
            Ah[k2][am]     = h0;
            Ah[k2 + 1][am] = h1;
            Al[k2][am]     = pack_bf2(l0x, l0y);
            Al[k2 + 1][am] = pack_bf2(l1z, l1w);
        }
        {
            float4 r0 = *(const float4*)(wptr + (size_t)k0 * Dd);
            float4 r1 = *(const float4*)(wptr + (size_t)(k0 + 1) * Dd);
            float f0[4] = {r0.x, r0.y, r0.z, r0.w};
            float f1[4] = {r1.x, r1.y, r1.z, r1.w};
            #pragma unroll
            for (int j = 0; j < 4; j++) {
                unsigned hp = pack_bf2(f0[j], f1[j]);
                float lo0 = f0[j] - __uint_as_float(hp << 16);
                float lo1 = f1[j] - __uint_as_float(hp & 0xffff0000u);
                Bh[kp][n4 + j] = hp;
                Bl[kp][n4 + j] = pack_bf2(lo0, lo1);
            }
        }
        __syncthreads();

        #pragma unroll
        for (int ks = 0; ks < 2; ks++) {
            const int kb = ks * 8;
            unsigned ah[2][4], al[2][4], bhf[4][2], blf[4][2];
            #pragma unroll
            for (int mt = 0; mt < 2; mt++) {
                const int mr = wm * 32 + mt * 16;
                ah[mt][0] = Ah[kb + tg][mr + g];
                ah[mt][1] = Ah[kb + tg][mr + g + 8];
                ah[mt][2] = Ah[kb + tg + 4][mr + g];
                ah[mt][3] = Ah[kb + tg + 4][mr + g + 8];
                al[mt][0] = Al[kb + tg][mr + g];
                al[mt][1] = Al[kb + tg][mr + g + 8];
                al[mt][2] = Al[kb + tg + 4][mr + g];
                al[mt][3] = Al[kb + tg + 4][mr + g + 8];
            }
            #pragma unroll
            for (int nt = 0; nt < 4; nt++) {
                const int nc = wn * 32 + nt * 8 + g;
                bhf[nt][0] = Bh[kb + tg][nc];
                bhf[nt][1] = Bh[kb + tg + 4][nc];
                blf[nt][0] = Bl[kb + tg][nc];
                blf[nt][1] = Bl[kb + tg + 4][nc];
            }
            #pragma unroll
            for (int mt = 0; mt < 2; mt++)
                #pragma unroll
                for (int nt = 0; nt < 4; nt++) {
                    mma16bf(acc[mt][nt], ah[mt], bhf[nt]);
                    mma16bf(acc[mt][nt], al[mt], bhf[nt]);
                    mma16bf(acc[mt][nt], ah[mt], blf[nt]);
                }
        }
        __syncthreads();
    }

    #pragma unroll
    for (int mt = 0; mt < 2; mt++)
        #pragma unroll
        for (int j2 = 0; j2 < 2; j2++) {
            const int m = m0 + wm * 32 + mt * 16 + g + j2 * 8;
            const int b = m / bt, t = m % bt;
            #pragma unroll
            for (int nt = 0; nt < 4; nt++) {
                const int n = n0 + wn * 32 + nt * 8 + 2 * tg;
                const float c0 = acc[mt][nt][j2 * 2 + 0] + bias[n];
                const float c1 = acc[mt][nt][j2 * 2 + 1] + bias[n + 1];
                if (mode == 0) {
                    *(float2*)&Out[(size_t)m * Dd + n] = make_float2(c0, c1);
                } else {
                    const int h = n >> 6, dd = n & 63;
                    *(float2*)&Out[(((size_t)b * Hh + h) * Lout + out_tok_off + t) * HD + dd] =
                        make_float2(c0, c1);
                }
            }
        }
}

// ---------------------------------------------------------------------------
// Per-token projections (unchanged from R3).
// ---------------------------------------------------------------------------
__global__ __launch_bounds__(256) void ns_proj(
    const float* __restrict__ x, const float* __restrict__ nw,
    const float* __restrict__ nb, float* __restrict__ Out,
    int Lout, int out_tok_off)
{
    const int n    = blockIdx.x;
    const int tid  = threadIdx.x;
    const int cgrp = tid & 31;
    const int kh   = tid >> 5;
    const int kbeg = kh * 64;
    const int colb = blockIdx.y * 128;

    __shared__ float xs[8][512];
    __shared__ float red[8][8][128];

    for (int i = tid; i < 8 * 512; i += 256) {
        const int b = i >> 9, k = i & 511;
        xs[b][k] = x[((size_t)b * LL + LS + n) * Dd + k];
    }
    __syncthreads();

    const float4* wp4 = (const float4*)(nw + (size_t)n * Dd * Dd) + (colb >> 2) + cgrp;

    float acc[8][4];
    #pragma unroll
    for (int b = 0; b < 8; b++)
        #pragma unroll
        for (int j = 0; j < 4; j++) acc[b][j] = 0.f;

    for (int k = 0; k < 64; k += 8) {
        float4 w[8];
        #pragma unroll
        for (int u = 0; u < 8; u++)
            w[u] = wp4[(size_t)(kbeg + k + u) * 128];
        #pragma unroll
        for (int u = 0; u < 8; u++) {
            #pragma unroll
            for (int b = 0; b < 8; b++) {
                const float s = xs[b][kbeg + k + u];
                acc[b][0] += s * w[u].x;
                acc[b][1] += s * w[u].y;
                acc[b][2] += s * w[u].z;
                acc[b][3] += s * w[u].w;
            }
        }
    }

    #pragma unroll
    for (int b = 0; b < 8; b++)
        *(float4*)&red[kh][b][cgrp * 4] =
            make_float4(acc[b][0], acc[b][1], acc[b][2], acc[b][3]);
    __syncthreads();

    for (int i = tid; i < 8 * 128; i += 256) {
        const int b = i >> 7, c = i & 127;
        float s = 0.f;
        #pragma unroll
        for (int k8 = 0; k8 < 8; k8++) s += red[k8][b][c];
        const int col = colb + c;
        const int h = col >> 6, dd = col & 63;
        Out[(((size_t)b * Hh + h) * Lout + out_tok_off + n) * HD + dd] =
            s + nb[(size_t)n * Dd + col];
    }
}

// ---------------------------------------------------------------------------
// Flash attention v2: raw fp32 bits into tf32 MMA (rz), Q/K row-major + cp.async,
// V transposed raw. grid (9, 64), 128 threads.
// ---------------------------------------------------------------------------
#define ATTN_SMEM ((3 * 64 * 68 + 64) * 4)

__global__ __launch_bounds__(128) void attn_tc(
    const float* __restrict__ Q, const float* __restrict__ K,
    const float* __restrict__ V, const int* __restrict__ pad_mask,
    float* __restrict__ Outp)
{
    extern __shared__ float smf[];
    float* Qs = smf;                   // [64 rows][68] raw fp32
    float* Kt = smf + 64 * 68;         // [64 keys][68]
    float* Vt = Kt + 64 * 68;          // [64 dims][68] transposed
    float* pads = Vt + 64 * 68;

    const int tid  = threadIdx.x;
    const int lane = tid & 31, warp = tid >> 5;
    const int g = lane >> 2, tg = lane & 3;
    const int bh = blockIdx.y, b = bh >> 3, h = bh & 7;
    const int q0 = blockIdx.x << 6;

    const float* Qp = Q + ((size_t)bh * LQ + q0) * HD;
    const float* Kp = K + (size_t)bh * LK * HD;
    const float* Vp = V + (size_t)bh * LK * HD;

    const uint32_t qs_u = (uint32_t)__cvta_generic_to_shared(Qs);
    const uint32_t kt_u = (uint32_t)__cvta_generic_to_shared(Kt);

    // async-load Q tile (64 x 64 fp32, 16B chunks)
    #pragma unroll
    for (int i = 0; i < 8; i++) {
        const int idx = i * 128 + tid;
        const int r = idx >> 4, c = idx & 15;
        cp16(qs_u + r * 272 + c * 16, (const char*)Qp + (size_t)r * 256 + c * 16);
    }
    cp_commit();

    float o[8][4];
    #pragma unroll
    for (int nt = 0; nt < 8; nt++)
        #pragma unroll
        for (int j = 0; j < 4; j++) o[nt][j] = 0.f;
    float m_run[2] = {-1e30f, -1e30f};
    float l_run[2] = {0.f, 0.f};

    const int row0 = q0 + warp * 16 + g;
    const int ntiles = min(LK >> 6, ((q0 + 63 + DELTA) >> 6) + 1);
    const int mr = warp * 16;

    for (int kt = 0; kt < ntiles; kt++) {
        const int k0 = kt << 6;
        __syncthreads();
        // K tile via cp.async (row-major raw)
        #pragma unroll
        for (int i = 0; i < 8; i++) {
            const int idx = i * 128 + tid;
            const int r = idx >> 4, c = idx & 15;
            cp16(kt_u + r * 272 + c * 16,
                 (const char*)Kp + (size_t)(k0 + r) * 256 + c * 16);
        }
        cp_commit();
        // V tile transposed via LDG+STS (raw bits)
        {
            const int r = tid & 63, dg = (tid >> 6) << 2;
            #pragma unroll
            for (int i = 0; i < 8; i++) {
                const int d = dg + i * 8;
                float4 vv = *(const float4*)(Vp + (size_t)(k0 + r) * HD + d);
                Vt[(d + 0) * 68 + r] = vv.x;
                Vt[(d + 1) * 68 + r] = vv.y;
                Vt[(d + 2) * 68 + r] = vv.z;
                Vt[(d + 3) * 68 + r] = vv.w;
            }
            if (tid < 64) {
                const int jg = k0 + tid;
                pads[tid] = (jg >= LS) ? 1.f : (pad_mask[(size_t)b * LS + jg] ? 1.f : 0.f);
            }
        }
        cp_wait0();
        __syncthreads();

        // ---- S = Q K^T (raw-bit tf32) ----
        float sc[8][4];
        #pragma unroll
        for (int nt = 0; nt < 8; nt++)
            #pragma unroll
            for (int j = 0; j < 4; j++) sc[nt][j] = 0.f;

        #pragma unroll
        for (int ks = 0; ks < 8; ks++) {
            unsigned a[4];
            a[0] = __float_as_uint(Qs[(mr + g) * 68 + ks * 8 + tg]);
            a[1] = __float_as_uint(Qs[(mr + g + 8) * 68 + ks * 8 + tg]);
            a[2] = __float_as_uint(Qs[(mr + g) * 68 + ks * 8 + tg + 4]);
            a[3] = __float_as_uint(Qs[(mr + g + 8) * 68 + ks * 8 + tg + 4]);
            #pragma unroll
            for (int nt = 0; nt < 8; nt++) {
                unsigned bb[2];
                bb[0] = __float_as_uint(Kt[(nt * 8 + g) * 68 + ks * 8 + tg]);
                bb[1] = __float_as_uint(Kt[(nt * 8 + g) * 68 + ks * 8 + tg + 4]);
                mma8(sc[nt], a, bb);
            }
        }

        // ---- scale + mask + online softmax ----
        float mx0 = -1e30f, mx1 = -1e30f;
        #pragma unroll
        for (int nt = 0; nt < 8; nt++) {
            sc[nt][0] *= 0.125f; sc[nt][1] *= 0.125f;
            sc[nt][2] *= 0.125f; sc[nt][3] *= 0.125f;
            const int cb = k0 + nt * 8 + 2 * tg;
            const float p0 = pads[nt * 8 + 2 * tg];
            const float p1 = pads[nt * 8 + 2 * tg + 1];
            if (cb     > row0 + DELTA     || p0 == 0.f) sc[nt][0] = -1e9f;
            if (cb + 1 > row0 + DELTA     || p1 == 0.f) sc[nt][1] = -1e9f;
            if (cb     > row0 + 8 + DELTA || p0 == 0.f) sc[nt][2] = -1e9f;
            if (cb + 1 > row0 + 8 + DELTA || p1 == 0.f) sc[nt][3] = -1e9f;
            mx0 = fmaxf(mx0, fmaxf(sc[nt][0], sc[nt][1]));
            mx1 = fmaxf(mx1, fmaxf(sc[nt][2], sc[nt][3]));
        }
        mx0 = fmaxf(mx0, __shfl_xor_sync(0xffffffffu, mx0, 1));
        mx0 = fmaxf(mx0, __shfl_xor_sync(0xffffffffu, mx0, 2));
        mx1 = fmaxf(mx1, __shfl_xor_sync(0xffffffffu, mx1, 1));
        mx1 = fmaxf(mx1, __shfl_xor_sync(0xffffffffu, mx1, 2));

        const float mn0 = fmaxf(m_run[0], mx0);
        const float mn1 = fmaxf(m_run[1], mx1);
        const float cr0 = __expf(m_run[0] - mn0);
        const float cr1 = __expf(m_run[1] - mn1);

        float ls0 = 0.f, ls1 = 0.f;
        #pragma unroll
        for (int nt = 0; nt < 8; nt++) {
            sc[nt][0] = __expf(sc[nt][0] - mn0); ls0 += sc[nt][0];
            sc[nt][1] = __expf(sc[nt][1] - mn0); ls0 += sc[nt][1];
            sc[nt][2] = __expf(sc[nt][2] - mn1); ls1 += sc[nt][2];
            sc[nt][3] = __expf(sc[nt][3] - mn1); ls1 += sc[nt][3];
        }
        ls0 += __shfl_xor_sync(0xffffffffu, ls0, 1);
        ls0 += __shfl_xor_sync(0xffffffffu, ls0, 2);
        ls1 += __shfl_xor_sync(0xffffffffu, ls1, 1);
        ls1 += __shfl_xor_sync(0xffffffffu, ls1, 2);

        l_run[0] = l_run[0] * cr0 + ls0;
        l_run[1] = l_run[1] * cr1 + ls1;
        m_run[0] = mn0; m_run[1] = mn1;

        #pragma unroll
        for (int nt = 0; nt < 8; nt++) {
            o[nt][0] *= cr0; o[nt][1] *= cr0;
            o[nt][2] *= cr1; o[nt][3] *= cr1;
        }

        // ---- O += P V ---- (P fragments via quad shuffles, raw bits)
        #pragma unroll
        for (int ks = 0; ks < 8; ks++) {
            const int s0 = (lane & ~3) | (tg >> 1);
            const int s1 = s0 + 2;
            unsigned a[4];
            {
                float e0 = __shfl_sync(0xffffffffu, sc[ks][0], s0);
                float e1 = __shfl_sync(0xffffffffu, sc[ks][1], s0);
                a[0] = __float_as_uint((tg & 1) ? e1 : e0);
                float e2 = __shfl_sync(0xffffffffu, sc[ks][2], s0);
                float e3 = __shfl_sync(0xffffffffu, sc[ks][3], s0);
                a[1] = __float_as_uint((tg & 1) ? e3 : e2);
                float f0 = __shfl_sync(0xffffffffu, sc[ks][0], s1);
                float f1 = __shfl_sync(0xffffffffu, sc[ks][1], s1);
                a[2] = __float_as_uint((tg & 1) ? f1 : f0);
                float f2v = __shfl_sync(0xffffffffu, sc[ks][2], s1);
                float f3v = __shfl_sync(0xffffffffu, sc[ks][3], s1);
                a[3] = __float_as_uint((tg & 1) ? f3v : f2v);
            }
            #pragma unroll
            for (int nt = 0; nt < 8; nt++) {
                unsigned bb[2];
                bb[0] = __float_as_uint(Vt[(nt * 8 + g) * 68 + ks * 8 + tg]);
                bb[1] = __float_as_uint(Vt[(nt * 8 + g) * 68 + ks * 8 + tg + 4]);
                mma8(o[nt], a, bb);
            }
        }
    }

    const float inv0 = (l_run[0] > 0.f) ? 1.f / l_run[0] : 0.f;
    const float inv1 = (l_run[1] > 0.f) ? 1.f / l_run[1] : 0.f;
    float* op0 = Outp + ((size_t)b * LQ + row0) * Dd + h * HD;
    float* op1 = op0 + (size_t)8 * Dd;
    #pragma unroll
    for (int nt = 0; nt < 8; nt++) {
        const int dc = nt * 8 + 2 * tg;
        *(float2*)(op0 + dc) = make_float2(o[nt][0] * inv0, o[nt][1] * inv0);
        *(float2*)(op1 + dc) = make_float2(o[nt][2] * inv1, o[nt][3] * inv1);
    }
}

// ---------------------------------------------------------------------------
extern "C" void kernel_launch(void* const* d_in, const int* in_sizes, int n_in,
                              void* d_out, int out_size)
{
    const float* x        = (const float*)d_in[0];
    const int*   pad_mask = (const int*)  d_in[1];
    const float* wq_sw = (const float*)d_in[4];
    const float* wq_sb = (const float*)d_in[5];
    const float* wq_nw = (const float*)d_in[6];
    const float* wq_nb = (const float*)d_in[7];
    const float* wk_sw = (const float*)d_in[8];
    const float* wk_sb = (const float*)d_in[9];
    const float* wk_nw = (const float*)d_in[10];
    const float* wk_nb = (const float*)d_in[11];
    const float* wv_sw = (const float*)d_in[12];
    const float* wv_sb = (const float*)d_in[13];
    const float* wv_nw = (const float*)d_in[14];
    const float* wv_nb = (const float*)d_in[15];
    const float* out_w = (const float*)d_in[16];
    const float* out_b = (const float*)d_in[17];
    float* out = (float*)d_out;

    float *pQ, *pK, *pV, *pA;
    cudaGetSymbolAddress((void**)&pQ, g_Q);
    cudaGetSymbolAddress((void**)&pK, g_K);
    cudaGetSymbolAddress((void**)&pV, g_V);
    cudaGetSymbolAddress((void**)&pA, g_attn);

    // 1: fused K+V projection
    gemm_tc<<<dim3(8, 128, 2), 256>>>(x, wk_sw, wk_sb, pK, wv_sw, wv_sb, pV,
                                      LS, 0, LL, 1, LK, 0);
    // 2: Q projection
    gemm_tc<<<dim3(8, 32, 1), 256>>>(x, wq_sw, wq_sb, pQ, wq_sw, wq_sb, pQ,
                                     LSO, LS - LSO, LL, 1, LQ, 0);
    // 3-5: per-token projections
    ns_proj<<<dim3(64, 4), 256>>>(x, wq_nw, wq_nb, pQ, LQ, LSO);
    ns_proj<<<dim3(64, 4), 256>>>(x, wk_nw, wk_nb, pK, LK, LS);
    ns_proj<<<dim3(64, 4), 256>>>(x, wv_nw, wv_nb, pV, LK, LS);

    // 6: attention (profiled launch: -s 5 -c 1)
    cudaFuncSetAttribute(attn_tc, cudaFuncAttributeMaxDynamicSharedMemorySize, ATTN_SMEM);
    attn_tc<<<dim3(LQ / 64, Bc * Hh), 128, ATTN_SMEM>>>(pQ, pK, pV, pad_mask, pA);

    // 7: output projection
    gemm_tc<<<dim3(8, 36, 1), 256>>>(pA, out_w, out_b, out, out_w, out_b, out,
                                     LQ, 0, LQ, 0, 0, 0);
}

// round 8
// speedup vs baseline: 1.1151x; 1.1151x over previous
#include <cuda_runtime.h>
#include <cuda_bf16.h>
#include <cstdint>
#include <math.h>

#define Bc 8
#define Hh 8
#define Dd 512
#define HD 64
#define LNS 64
#define LS 2048
#define LSO 512
#define LQ (LSO + LNS)   // 576
#define LK (LS + LNS)    // 2112
#define LL (LS + LNS)
#define DELTA (LK - LQ)  // 1536

__device__ float g_Q[(size_t)Bc * Hh * LQ * HD];
__device__ float g_K[(size_t)Bc * Hh * LK * HD];
__device__ float g_V[(size_t)Bc * Hh * LK * HD];
__device__ float g_attn[(size_t)Bc * LQ * Dd];
// packed bf16x2 split operands, row-major [row][k2=256] (k-pairs)
__device__ unsigned g_x2h[(size_t)Bc * LS * 256];
__device__ unsigned g_x2l[(size_t)Bc * LS * 256];
__device__ unsigned g_w2h[(size_t)4 * Dd * 256];   // W^T [mat][n][k2]
__device__ unsigned g_w2l[(size_t)4 * Dd * 256];
__device__ unsigned g_a2h[(size_t)Bc * LQ * 256];
__device__ unsigned g_a2l[(size_t)Bc * LQ * 256];

// ---------------- helpers ----------------
__device__ __forceinline__ unsigned f2tf(float f) {
    unsigned u; asm("cvt.rna.tf32.f32 %0, %1;" : "=r"(u) : "f"(f)); return u;
}
__device__ __forceinline__ void mma8(float* c, const unsigned* a, const unsigned* b) {
    asm volatile("mma.sync.aligned.m16n8k8.row.col.f32.tf32.tf32.f32 "
        "{%0,%1,%2,%3},{%4,%5,%6,%7},{%8,%9},{%0,%1,%2,%3};\n"
        : "+f"(c[0]), "+f"(c[1]), "+f"(c[2]), "+f"(c[3])
        : "r"(a[0]), "r"(a[1]), "r"(a[2]), "r"(a[3]), "r"(b[0]), "r"(b[1]));
}
__device__ __forceinline__ void mma16bf(float* c, const unsigned* a, const unsigned* b) {
    asm volatile("mma.sync.aligned.m16n8k16.row.col.f32.bf16.bf16.f32 "
        "{%0,%1,%2,%3},{%4,%5,%6,%7},{%8,%9},{%0,%1,%2,%3};\n"
        : "+f"(c[0]), "+f"(c[1]), "+f"(c[2]), "+f"(c[3])
        : "r"(a[0]), "r"(a[1]), "r"(a[2]), "r"(a[3]), "r"(b[0]), "r"(b[1]));
}
__device__ __forceinline__ unsigned pack_bf2(float f0, float f1) {
    unsigned r; asm("cvt.rn.bf16x2.f32 %0, %1, %2;" : "=r"(r) : "f"(f1), "f"(f0)); return r;
}
__device__ __forceinline__ void cp16(uint32_t sdst, const void* gsrc) {
    asm volatile("cp.async.ca.shared.global [%0], [%1], 16;\n" :: "r"(sdst), "l"(gsrc));
}
__device__ __forceinline__ void cp_commit() { asm volatile("cp.async.commit_group;\n" ::: "memory"); }
__device__ __forceinline__ void cp_wait1()  { asm volatile("cp.async.wait_group 1;\n" ::: "memory"); }
__device__ __forceinline__ uint32_t smem_u32(const void* p) {
    uint32_t a; asm("{ .reg .u64 t; cvta.to.shared.u64 t, %1; cvt.u32.u64 %0, t; }" : "=r"(a) : "l"(p)); return a;
}
__device__ __forceinline__ void split2(float f0, float f1, unsigned& h, unsigned& l) {
    h = pack_bf2(f0, f1);
    l = pack_bf2(f0 - __uint_as_float(h << 16), f1 - __uint_as_float(h & 0xffff0000u));
}

// ---------------- converters ----------------
__global__ __launch_bounds__(256) void conv_in(
    const float* __restrict__ x, const float* __restrict__ w0, const float* __restrict__ w1,
    const float* __restrict__ w2, const float* __restrict__ w3)
{
    const int gid = blockIdx.x * 256 + threadIdx.x;
    if (blockIdx.x < 8192) {                    // x rows (b*2048 + t)
        const int row = gid >> 7, col = (gid & 127) << 2;
        const int b = row >> 11, t = row & 2047;
        float4 v = *(const float4*)(x + ((size_t)b * LL + t) * Dd + col);
        unsigned h0, l0, h1, l1;
        split2(v.x, v.y, h0, l0);
        split2(v.z, v.w, h1, l1);
        *(uint2*)&g_x2h[(size_t)row * 256 + (col >> 1)] = make_uint2(h0, h1);
        *(uint2*)&g_x2l[(size_t)row * 256 + (col >> 1)] = make_uint2(l0, l1);
    } else {                                    // W^T
        const int idx = gid - 8192 * 256;
        if (idx >= 4 * 512 * 64) return;
        const int n = idx & 511, k8 = (idx >> 9) & 63, mat = idx >> 15;
        const float* W = (mat == 0) ? w0 : (mat == 1) ? w1 : (mat == 2) ? w2 : w3;
        unsigned hh[4], ll[4];
        #pragma unroll
        for (int j = 0; j < 4; j++) {
            const float f0 = W[(size_t)(k8 * 8 + 2 * j) * Dd + n];
            const float f1 = W[(size_t)(k8 * 8 + 2 * j + 1) * Dd + n];
            split2(f0, f1, hh[j], ll[j]);
        }
        const size_t o = ((size_t)mat * 512 + n) * 256 + k8 * 4;
        *(uint4*)&g_w2h[o] = make_uint4(hh[0], hh[1], hh[2], hh[3]);
        *(uint4*)&g_w2l[o] = make_uint4(ll[0], ll[1], ll[2], ll[3]);
    }
}

__global__ __launch_bounds__(256) void conv_attn(const float* __restrict__ A)
{
    const int gid = blockIdx.x * 256 + threadIdx.x;   // 4608 rows * 128
    const int row = gid >> 7, col = (gid & 127) << 2;
    float4 v = *(const float4*)(A + (size_t)row * Dd + col);
    unsigned h0, l0, h1, l1;
    split2(v.x, v.y, h0, l0);
    split2(v.z, v.w, h1, l1);
    *(uint2*)&g_a2h[(size_t)row * 256 + (col >> 1)] = make_uint2(h0, h1);
    *(uint2*)&g_a2l[(size_t)row * 256 + (col >> 1)] = make_uint2(l0, l1);
}

// ---------------- pipelined split-bf16 GEMM ----------------
// 128m x 64n tile, 16 chunks of k2=16 (k=32), 2-stage cp.async pipeline.
// smem byte offsets (rows padded to 20 words = 80B)
#define B_AH 0u          // [2][128][20]
#define B_AL 20480u
#define B_BH 40960u      // [2][64][20]
#define B_BL 51200u
#define GS_TOT 61440

__global__ __launch_bounds__(256) void gemm5(
    int w0i, int w1i,
    const float* __restrict__ bias0, float* __restrict__ out0, int rnd0,
    const float* __restrict__ bias1, float* __restrict__ out1, int rnd1,
    int bt, int tok_off, int mode, int Lout, int out_tok_off, int useAttn)
{
    extern __shared__ __align__(16) char smem[];
    const uint32_t sb = smem_u32(smem);
    const int tid = threadIdx.x;
    const int lane = tid & 31, warp = tid >> 5;
    const int wm = warp >> 1, wn = warp & 1;
    const int g = lane >> 2, tg = lane & 3;
    const int m0 = blockIdx.y << 7, n0 = blockIdx.x << 6;
    const int widx = (blockIdx.z == 0) ? w0i : w1i;
    const float* bias = (blockIdx.z == 0) ? bias0 : bias1;
    float*       Out  = (blockIdx.z == 0) ? out0  : out1;
    const int    rnd  = (blockIdx.z == 0) ? rnd0  : rnd1;

    const int arow0 = useAttn ? m0 : ((m0 / bt) * LS + tok_off + (m0 % bt));
    const char* aH = (const char*)(useAttn ? g_a2h : g_x2h) + (size_t)arow0 * 1024;
    const char* aL = (const char*)(useAttn ? g_a2l : g_x2l) + (size_t)arow0 * 1024;
    const char* bH = (const char*)g_w2h + ((size_t)widx * 512 + n0) * 1024;
    const char* bL = (const char*)g_w2l + ((size_t)widx * 512 + n0) * 1024;

    // loader mapping
    const int arow = tid >> 1;                    // 0..127
    const int ach0 = (tid & 1) * 2;               // 0 or 2 (+1 below)
    const int brow = tid >> 2;                    // 0..63
    const int bch  = tid & 3;

    float acc[2][4][4];
    #pragma unroll
    for (int a = 0; a < 2; a++)
        #pragma unroll
        for (int b = 0; b < 4; b++)
            #pragma unroll
            for (int c = 0; c < 4; c++) acc[a][b][c] = 0.f;

#define G_LOAD(c, st) { \
    const size_t ao = (size_t)arow * 1024 + (size_t)(c) * 64; \
    cp16(sb + B_AH + (st) * 10240u + arow * 80 + (ach0 + 0) * 16, aH + ao + (ach0 + 0) * 16); \
    cp16(sb + B_AH + (st) * 10240u + arow * 80 + (ach0 + 1) * 16, aH + ao + (ach0 + 1) * 16); \
    cp16(sb + B_AL + (st) * 10240u + arow * 80 + (ach0 + 0) * 16, aL + ao + (ach0 + 0) * 16); \
    cp16(sb + B_AL + (st) * 10240u + arow * 80 + (ach0 + 1) * 16, aL + ao + (ach0 + 1) * 16); \
    const size_t bo = (size_t)brow * 1024 + (size_t)(c) * 64 + bch * 16; \
    cp16(sb + B_BH + (st) * 5120u + brow * 80 + bch * 16, bH + bo); \
    cp16(sb + B_BL + (st) * 5120u + brow * 80 + bch * 16, bL + bo); \
    cp_commit(); }

    G_LOAD(0, 0);

    for (int c = 0; c < 16; c++) {
        const int nc = (c + 1 < 16) ? c + 1 : 15;
        G_LOAD(nc, (c + 1) & 1);
        cp_wait1();
        __syncthreads();

        const unsigned* A_h = (const unsigned*)(smem + B_AH + (c & 1) * 10240u);
        const unsigned* A_l = (const unsigned*)(smem + B_AL + (c & 1) * 10240u);
        const unsigned* Bh_ = (const unsigned*)(smem + B_BH + (c & 1) * 5120u);
        const unsigned* Bl_ = (const unsigned*)(smem + B_BH + (c & 1) * 5120u + (B_BL - B_BH));

        #pragma unroll
        for (int s2 = 0; s2 < 2; s2++) {
            const int k2o = s2 * 8;
            unsigned ah[2][4], al[2][4], bh[4][2], bl[4][2];
            #pragma unroll
            for (int mt = 0; mt < 2; mt++) {
                const int mr = wm * 32 + mt * 16;
                ah[mt][0] = A_h[(mr + g) * 20 + k2o + tg];
                ah[mt][1] = A_h[(mr + g + 8) * 20 + k2o + tg];
                ah[mt][2] = A_h[(mr + g) * 20 + k2o + tg + 4];
                ah[mt][3] = A_h[(mr + g + 8) * 20 + k2o + tg + 4];
                al[mt][0] = A_l[(mr + g) * 20 + k2o + tg];
                al[mt][1] = A_l[(mr + g + 8) * 20 + k2o + tg];
                al[mt][2] = A_l[(mr + g) * 20 + k2o + tg + 4];
                al[mt][3] = A_l[(mr + g + 8) * 20 + k2o + tg + 4];
            }
            #pragma unroll
            for (int nt = 0; nt < 4; nt++) {
                const int nc2 = wn * 32 + nt * 8 + g;
                bh[nt][0] = Bh_[nc2 * 20 + k2o + tg];
                bh[nt][1] = Bh_[nc2 * 20 + k2o + tg + 4];
                bl[nt][0] = Bl_[nc2 * 20 + k2o + tg];
                bl[nt][1] = Bl_[nc2 * 20 + k2o + tg + 4];
            }
            #pragma unroll
            for (int mt = 0; mt < 2; mt++)
                #pragma unroll
                for (int nt = 0; nt < 4; nt++) {
                    mma16bf(acc[mt][nt], ah[mt], bh[nt]);
                    mma16bf(acc[mt][nt], al[mt], bh[nt]);
                    mma16bf(acc[mt][nt], ah[mt], bl[nt]);
                }
        }
        __syncthreads();
    }

    #pragma unroll
    for (int mt = 0; mt < 2; mt++)
        #pragma unroll
        for (int j2 = 0; j2 < 2; j2++) {
            const int m = m0 + wm * 32 + mt * 16 + g + j2 * 8;
            const int b = m / bt, t = m % bt;
            #pragma unroll
            for (int nt = 0; nt < 4; nt++) {
                const int n = n0 + wn * 32 + nt * 8 + 2 * tg;
                float c0 = acc[mt][nt][j2 * 2 + 0] + bias[n];
                float c1 = acc[mt][nt][j2 * 2 + 1] + bias[n + 1];
                if (rnd) {
                    c0 = __uint_as_float(f2tf(c0));
                    c1 = __uint_as_float(f2tf(c1));
                }
                if (mode == 0) {
                    *(float2*)&Out[(size_t)m * Dd + n] = make_float2(c0, c1);
                } else {
                    const int h = n >> 6, dd = n & 63;
                    *(float2*)&Out[(((size_t)b * Hh + h) * Lout + out_tok_off + t) * HD + dd] =
                        make_float2(c0, c1);
                }
            }
        }
}

// ---------------- per-token projections (fused 3-in-1) ----------------
__global__ __launch_bounds__(256) void ns_proj(
    const float* __restrict__ x,
    const float* __restrict__ nw0, const float* __restrict__ nb0, float* __restrict__ o0,
    const float* __restrict__ nw1, const float* __restrict__ nb1, float* __restrict__ o1,
    const float* __restrict__ nw2, const float* __restrict__ nb2, float* __restrict__ o2)
{
    const int z = blockIdx.z;
    const float* nw = (z == 0) ? nw0 : (z == 1) ? nw1 : nw2;
    const float* nb = (z == 0) ? nb0 : (z == 1) ? nb1 : nb2;
    float* Out      = (z == 0) ? o0  : (z == 1) ? o1  : o2;
    const int Lout        = (z == 0) ? LQ  : LK;
    const int out_tok_off = (z == 0) ? LSO : LS;

    const int n = blockIdx.x, tid = threadIdx.x;
    const int cgrp = tid & 31, kh = tid >> 5, kbeg = kh * 64;
    const int colb = blockIdx.y * 128;

    __shared__ float xs[8][512];
    __shared__ float red[8][8][128];

    for (int i = tid; i < 8 * 512; i += 256) {
        const int b = i >> 9, k = i & 511;
        xs[b][k] = x[((size_t)b * LL + LS + n) * Dd + k];
    }
    __syncthreads();

    const float4* wp4 = (const float4*)(nw + (size_t)n * Dd * Dd) + (colb >> 2) + cgrp;
    float acc[8][4];
    #pragma unroll
    for (int b = 0; b < 8; b++)
        #pragma unroll
        for (int j = 0; j < 4; j++) acc[b][j] = 0.f;

    for (int k = 0; k < 64; k += 8) {
        float4 w[8];
        #pragma unroll
        for (int u = 0; u < 8; u++) w[u] = wp4[(size_t)(kbeg + k + u) * 128];
        #pragma unroll
        for (int u = 0; u < 8; u++)
            #pragma unroll
            for (int b = 0; b < 8; b++) {
                const float s = xs[b][kbeg + k + u];
                acc[b][0] += s * w[u].x; acc[b][1] += s * w[u].y;
                acc[b][2] += s * w[u].z; acc[b][3] += s * w[u].w;
            }
    }
    #pragma unroll
    for (int b = 0; b < 8; b++)
        *(float4*)&red[kh][b][cgrp * 4] = make_float4(acc[b][0], acc[b][1], acc[b][2], acc[b][3]);
    __syncthreads();

    for (int i = tid; i < 8 * 128; i += 256) {
        const int b = i >> 7, c = i & 127;
        float s = 0.f;
        #pragma unroll
        for (int k8 = 0; k8 < 8; k8++) s += red[k8][b][c];
        const int col = colb + c, h = col >> 6, dd = col & 63;
        float v = s + nb[(size_t)n * Dd + col];
        if (z == 2) v = __uint_as_float(f2tf(v));   // V pre-rounded to tf32-rn
        Out[(((size_t)b * Hh + h) * Lout + out_tok_off + n) * HD + dd] = v;
    }
}

// ---------------- flash attention: Q-in-regs, double-buffered K/V ----------------
// K rows stride 68 floats; V rows stride 72 floats (conflict-free fragments)
#define A_KST 68
#define A_VST 72
#define A_VOFF (2 * 64 * A_KST)                 // floats
#define A_POFF (A_VOFF + 2 * 64 * A_VST)
#define ATTN_SMEM (A_POFF * 4 + 2 * 64 * 4)

__global__ __launch_bounds__(128) void attn_tc(
    const float* __restrict__ Q, const float* __restrict__ K,
    const float* __restrict__ V, const int* __restrict__ pad_mask,
    float* __restrict__ Outp)
{
    extern __shared__ __align__(16) float smf[];
    float* Ks = smf;
    float* Vs = smf + A_VOFF;
    int*   padi = (int*)(smf + A_POFF);

    const int tid = threadIdx.x, lane = tid & 31, warp = tid >> 5;
    const int g = lane >> 2, tg = lane & 3;
    const int bh = blockIdx.y, b = bh >> 3, h = bh & 7;
    const int q0 = blockIdx.x << 6;
    const int mr = warp * 16;

    const float* Qp = Q + ((size_t)bh * LQ + q0) * HD;
    const float* Kp = K + (size_t)bh * LK * HD;
    const float* Vp = V + (size_t)bh * LK * HD;
    const uint32_t ks_u = smem_u32(Ks);
    const uint32_t vs_u = smem_u32(Vs);
    const uint32_t pd_u = smem_u32(padi);

    // Q fragments in registers, scale folded, tf32-rn
    unsigned aq[8][4];
    #pragma unroll
    for (int ks = 0; ks < 8; ks++) {
        aq[ks][0] = f2tf(Qp[(size_t)(mr + g) * HD + ks * 8 + tg] * 0.125f);
        aq[ks][1] = f2tf(Qp[(size_t)(mr + g + 8) * HD + ks * 8 + tg] * 0.125f);
        aq[ks][2] = f2tf(Qp[(size_t)(mr + g) * HD + ks * 8 + tg + 4] * 0.125f);
        aq[ks][3] = f2tf(Qp[(size_t)(mr + g + 8) * HD + ks * 8 + tg + 4] * 0.125f);
    }

    float o[8][4];
    #pragma unroll
    for (int nt = 0; nt < 8; nt++)
        #pragma unroll
        for (int j = 0; j < 4; j++) o[nt][j] = 0.f;
    float m_run[2] = {-1e30f, -1e30f};
    float l_run[2] = {0.f, 0.f};

    const int row0 = q0 + mr + g;
    const int ntiles = min(LK >> 6, ((q0 + 63 + DELTA) >> 6) + 1);

#define A_LOAD(t, st) { \
    _Pragma("unroll") \
    for (int i = 0; i < 8; i++) { \
        const int idx = i * 128 + tid; \
        const int r = idx >> 4, ch = idx & 15; \
        cp16(ks_u + (st) * 17408u + r * 272u + ch * 16u, \
             (const char*)Kp + ((size_t)((t) * 64 + r)) * 256 + ch * 16); \
        cp16(vs_u + (st) * 18432u + r * 288u + ch * 16u, \
             (const char*)Vp + ((size_t)((t) * 64 + r)) * 256 + ch * 16); \
    } \
    if ((t) * 64 < LS) { \
        if (tid < 16) \
            cp16(pd_u + (st) * 256u + tid * 16u, \
                 (const char*)(pad_mask + (size_t)b * LS + (t) * 64) + tid * 16); \
    } else { \
        if (tid < 64) padi[(st) * 64 + tid] = 1; \
    } \
    cp_commit(); }

    A_LOAD(0, 0);

    for (int kt = 0; kt < ntiles; kt++) {
        const int nxt = (kt + 1 < ntiles) ? kt + 1 : ntiles - 1;
        A_LOAD(nxt, (kt + 1) & 1);
        cp_wait1();
        __syncthreads();

        const float* Kc = Ks + (kt & 1) * 64 * A_KST;
        const float* Vc = Vs + (kt & 1) * 64 * A_VST;
        const int*   pc = padi + (kt & 1) * 64;
        const int k0 = kt << 6;

        // ---- S = Q K^T ----
        float sc[8][4];
        #pragma unroll
        for (int nt = 0; nt < 8; nt++)
            #pragma unroll
            for (int j = 0; j < 4; j++) sc[nt][j] = 0.f;

        #pragma unroll
        for (int ks = 0; ks < 8; ks++)
            #pragma unroll
            for (int nt = 0; nt < 8; nt++) {
                unsigned bb[2];
                bb[0] = __float_as_uint(Kc[(nt * 8 + g) * A_KST + ks * 8 + tg]);
                bb[1] = __float_as_uint(Kc[(nt * 8 + g) * A_KST + ks * 8 + tg + 4]);
                mma8(sc[nt], aq[ks], bb);
            }

        // ---- mask + online softmax (scale folded into Q) ----
        float mx0 = -1e30f, mx1 = -1e30f;
        #pragma unroll
        for (int nt = 0; nt < 8; nt++) {
            const int cb = k0 + nt * 8 + 2 * tg;
            const int p0 = pc[nt * 8 + 2 * tg];
            const int p1 = pc[nt * 8 + 2 * tg + 1];
            if (cb     > row0 + DELTA     || !p0) sc[nt][0] = -1e9f;
            if (cb + 1 > row0 + DELTA     || !p1) sc[nt][1] = -1e9f;
            if (cb     > row0 + 8 + DELTA || !p0) sc[nt][2] = -1e9f;
            if (cb + 1 > row0 + 8 + DELTA || !p1) sc[nt][3] = -1e9f;
            mx0 = fmaxf(mx0, fmaxf(sc[nt][0], sc[nt][1]));
            mx1 = fmaxf(mx1, fmaxf(sc[nt][2], sc[nt][3]));
        }
        mx0 = fmaxf(mx0, __shfl_xor_sync(0xffffffffu, mx0, 1));
        mx0 = fmaxf(mx0, __shfl_xor_sync(0xffffffffu, mx0, 2));
        mx1 = fmaxf(mx1, __shfl_xor_sync(0xffffffffu, mx1, 1));
        mx1 = fmaxf(mx1, __shfl_xor_sync(0xffffffffu, mx1, 2));

        const float mn0 = fmaxf(m_run[0], mx0), mn1 = fmaxf(m_run[1], mx1);
        const float cr0 = __expf(m_run[0] - mn0), cr1 = __expf(m_run[1] - mn1);

        float ls0 = 0.f, ls1 = 0.f;
        #pragma unroll
        for (int nt = 0; nt < 8; nt++) {
            sc[nt][0] = __expf(sc[nt][0] - mn0); ls0 += sc[nt][0];
            sc[nt][1] = __expf(sc[nt][1] - mn0); ls0 += sc[nt][1];
            sc[nt][2] = __expf(sc[nt][2] - mn1); ls1 += sc[nt][2];
            sc[nt][3] = __expf(sc[nt][3] - mn1); ls1 += sc[nt][3];
        }
        ls0 += __shfl_xor_sync(0xffffffffu, ls0, 1);
        ls0 += __shfl_xor_sync(0xffffffffu, ls0, 2);
        ls1 += __shfl_xor_sync(0xffffffffu, ls1, 1);
        ls1 += __shfl_xor_sync(0xffffffffu, ls1, 2);

        l_run[0] = l_run[0] * cr0 + ls0;
        l_run[1] = l_run[1] * cr1 + ls1;
        m_run[0] = mn0; m_run[1] = mn1;

        #pragma unroll
        for (int nt = 0; nt < 8; nt++) {
            o[nt][0] *= cr0; o[nt][1] *= cr0;
            o[nt][2] *= cr1; o[nt][3] *= cr1;
        }

        // ---- O += P V  (P fragments via quad shuffles, tf32-rn) ----
        #pragma unroll
        for (int ks = 0; ks < 8; ks++) {
            const int s0 = (lane & ~3) | (tg >> 1);
            const int s1 = s0 + 2;
            unsigned a[4];
            {
                float e0 = __shfl_sync(0xffffffffu, sc[ks][0], s0);
                float e1 = __shfl_sync(0xffffffffu, sc[ks][1], s0);
                a[0] = f2tf((tg & 1) ? e1 : e0);
                float e2 = __shfl_sync(0xffffffffu, sc[ks][2], s0);
                float e3 = __shfl_sync(0xffffffffu, sc[ks][3], s0);
                a[1] = f2tf((tg & 1) ? e3 : e2);
                float f0 = __shfl_sync(0xffffffffu, sc[ks][0], s1);
                float f1 = __shfl_sync(0xffffffffu, sc[ks][1], s1);
                a[2] = f2tf((tg & 1) ? f1 : f0);
                float f2v = __shfl_sync(0xffffffffu, sc[ks][2], s1);
                float f3v = __shfl_sync(0xffffffffu, sc[ks][3], s1);
                a[3] = f2tf((tg & 1) ? f3v : f2v);
            }
            #pragma unroll
            for (int nt = 0; nt < 8; nt++) {
                unsigned bb[2];
                bb[0] = __float_as_uint(Vc[(ks * 8 + tg) * A_VST + nt * 8 + g]);
                bb[1] = __float_as_uint(Vc[(ks * 8 + tg + 4) * A_VST + nt * 8 + g]);
                mma8(o[nt], a, bb);
            }
        }
        __syncthreads();
    }

    const float inv0 = (l_run[0] > 0.f) ? 1.f / l_run[0] : 0.f;
    const float inv1 = (l_run[1] > 0.f) ? 1.f / l_run[1] : 0.f;
    float* op0 = Outp + ((size_t)b * LQ + row0) * Dd + h * HD;
    float* op1 = op0 + (size_t)8 * Dd;
    #pragma unroll
    for (int nt = 0; nt < 8; nt++) {
        const int dc = nt * 8 + 2 * tg;
        *(float2*)(op0 + dc) = make_float2(o[nt][0] * inv0, o[nt][1] * inv0);
        *(float2*)(op1 + dc) = make_float2(o[nt][2] * inv1, o[nt][3] * inv1);
    }
}

// ---------------------------------------------------------------------------
extern "C" void kernel_launch(void* const* d_in, const int* in_sizes, int n_in,
                              void* d_out, int out_size)
{
    const float* x        = (const float*)d_in[0];
    const int*   pad_mask = (const int*)  d_in[1];
    const float* wq_sw = (const float*)d_in[4];
    const float* wq_sb = (const float*)d_in[5];
    const float* wq_nw = (const float*)d_in[6];
    const float* wq_nb = (const float*)d_in[7];
    const float* wk_sw = (const float*)d_in[8];
    const float* wk_sb = (const float*)d_in[9];
    const float* wk_nw = (const float*)d_in[10];
    const float* wk_nb = (const float*)d_in[11];
    const float* wv_sw = (const float*)d_in[12];
    const float* wv_sb = (const float*)d_in[13];
    const float* wv_nw = (const float*)d_in[14];
    const float* wv_nb = (const float*)d_in[15];
    const float* out_w = (const float*)d_in[16];
    const float* out_b = (const float*)d_in[17];
    float* out = (float*)d_out;

    float *pQ, *pK, *pV, *pA;
    cudaGetSymbolAddress((void**)&pQ, g_Q);
    cudaGetSymbolAddress((void**)&pK, g_K);
    cudaGetSymbolAddress((void**)&pV, g_V);
    cudaGetSymbolAddress((void**)&pA, g_attn);

    cudaFuncSetAttribute(gemm5, cudaFuncAttributeMaxDynamicSharedMemorySize, GS_TOT);
    cudaFuncSetAttribute(attn_tc, cudaFuncAttributeMaxDynamicSharedMemorySize, ATTN_SMEM);

    // 1: pre-split x + 4 weight matrices into packed bf16x2 hi/lo
    conv_in<<<8704, 256>>>(x, wq_sw, wk_sw, wv_sw, out_w);
    // 2: K+V projections (pipelined bf16 MMA); V rounded to tf32-rn in epilogue
    gemm5<<<dim3(8, 128, 2), 256, GS_TOT>>>(1, 2, wk_sb, pK, 0, wv_sb, pV, 1,
                                            LS, 0, 1, LK, 0, 0);
    // 3: Q projection
    gemm5<<<dim3(8, 32, 1), 256, GS_TOT>>>(0, 0, wq_sb, pQ, 0, wq_sb, pQ, 0,
                                           LSO, LS - LSO, 1, LQ, 0, 0);
    // 4: per-token projections (fused; V branch rounds)
    ns_proj<<<dim3(64, 4, 3), 256>>>(x, wq_nw, wq_nb, pQ, wk_nw, wk_nb, pK,
                                     wv_nw, wv_nb, pV);
    // 5: attention  <-- profiled launch
    attn_tc<<<dim3(LQ / 64, Bc * Hh), 128, ATTN_SMEM>>>(pQ, pK, pV, pad_mask, pA);
    // 6: split attn output
    conv_attn<<<2304, 256>>>(pA);
    // 7: output projection
    gemm5<<<dim3(8, 36, 1), 256, GS_TOT>>>(3, 3, out_b, out, 0, out_b, out, 0,
                                           LQ, 0, 0, 0, 0, 1);
}

// round 9
// speedup vs baseline: 1.1724x; 1.0514x over previous
#include <cuda_runtime.h>
#include <cuda_fp16.h>
#include <cstdint>
#include <math.h>

#define Bc 8
#define Hh 8
#define Dd 512
#define HD 64
#define LNS 64
#define LS 2048
#define LSO 512
#define LQ (LSO + LNS)   // 576
#define LK (LS + LNS)    // 2112
#define LL (LS + LNS)
#define DELTA (LK - LQ)  // 1536

__device__ float g_Q[(size_t)Bc * Hh * LQ * HD];
__device__ float g_K[(size_t)Bc * Hh * LK * HD];
__device__ float g_V[(size_t)Bc * Hh * LK * HD];
__device__ float g_attn[(size_t)Bc * LQ * Dd];
// packed fp16x2 split operands, row-major [row][k2=256]
__device__ unsigned g_x2h[(size_t)Bc * LS * 256];
__device__ unsigned g_x2l[(size_t)Bc * LS * 256];
__device__ unsigned g_w2h[(size_t)4 * Dd * 256];   // W^T [mat][n][k2], hi only
__device__ unsigned g_a2h[(size_t)Bc * LQ * 256];
__device__ unsigned g_a2l[(size_t)Bc * LQ * 256];

// ---------------- helpers ----------------
__device__ __forceinline__ unsigned f2tf(float f) {
    unsigned u; asm("cvt.rna.tf32.f32 %0, %1;" : "=r"(u) : "f"(f)); return u;
}
__device__ __forceinline__ void mma8(float* c, const unsigned* a, const unsigned* b) {
    asm volatile("mma.sync.aligned.m16n8k8.row.col.f32.tf32.tf32.f32 "
        "{%0,%1,%2,%3},{%4,%5,%6,%7},{%8,%9},{%0,%1,%2,%3};\n"
        : "+f"(c[0]), "+f"(c[1]), "+f"(c[2]), "+f"(c[3])
        : "r"(a[0]), "r"(a[1]), "r"(a[2]), "r"(a[3]), "r"(b[0]), "r"(b[1]));
}
__device__ __forceinline__ void mma16h(float* c, const unsigned* a, const unsigned* b) {
    asm volatile("mma.sync.aligned.m16n8k16.row.col.f32.f16.f16.f32 "
        "{%0,%1,%2,%3},{%4,%5,%6,%7},{%8,%9},{%0,%1,%2,%3};\n"
        : "+f"(c[0]), "+f"(c[1]), "+f"(c[2]), "+f"(c[3])
        : "r"(a[0]), "r"(a[1]), "r"(a[2]), "r"(a[3]), "r"(b[0]), "r"(b[1]));
}
__device__ __forceinline__ void cp16(uint32_t sdst, const void* gsrc) {
    asm volatile("cp.async.ca.shared.global [%0], [%1], 16;\n" :: "r"(sdst), "l"(gsrc));
}
__device__ __forceinline__ void cp_commit() { asm volatile("cp.async.commit_group;\n" ::: "memory"); }
__device__ __forceinline__ void cp_wait1()  { asm volatile("cp.async.wait_group 1;\n" ::: "memory"); }
__device__ __forceinline__ uint32_t smem_u32(const void* p) {
    uint32_t a; asm("{ .reg .u64 t; cvta.to.shared.u64 t, %1; cvt.u32.u64 %0, t; }" : "=r"(a) : "l"(p)); return a;
}
// fp16 hi/lo split: h = f16x2(f0,f1) (f0 low), l = f16x2(residuals)
__device__ __forceinline__ void split2h(float f0, float f1, unsigned& h, unsigned& l) {
    __half2 hh = __floats2half2_rn(f0, f1);
    float r0 = f0 - __half2float(__low2half(hh));
    float r1 = f1 - __half2float(__high2half(hh));
    __half2 ll = __floats2half2_rn(r0, r1);
    h = *reinterpret_cast<unsigned*>(&hh);
    l = *reinterpret_cast<unsigned*>(&ll);
}
__device__ __forceinline__ unsigned packh(float f0, float f1) {
    __half2 hh = __floats2half2_rn(f0, f1);
    return *reinterpret_cast<unsigned*>(&hh);
}

// ---------------- converters ----------------
__global__ __launch_bounds__(256) void conv_in(
    const float* __restrict__ x, const float* __restrict__ w0, const float* __restrict__ w1,
    const float* __restrict__ w2, const float* __restrict__ w3)
{
    const int gid = blockIdx.x * 256 + threadIdx.x;
    if (blockIdx.x < 8192) {                    // x rows (b*2048 + t)
        const int row = gid >> 7, col = (gid & 127) << 2;
        const int b = row >> 11, t = row & 2047;
        float4 v = *(const float4*)(x + ((size_t)b * LL + t) * Dd + col);
        unsigned h0, l0, h1, l1;
        split2h(v.x, v.y, h0, l0);
        split2h(v.z, v.w, h1, l1);
        *(uint2*)&g_x2h[(size_t)row * 256 + (col >> 1)] = make_uint2(h0, h1);
        *(uint2*)&g_x2l[(size_t)row * 256 + (col >> 1)] = make_uint2(l0, l1);
    } else {                                    // W^T (hi only)
        const int idx = gid - 8192 * 256;
        if (idx >= 4 * 512 * 64) return;
        const int n = idx & 511, k8 = (idx >> 9) & 63, mat = idx >> 15;
        const float* W = (mat == 0) ? w0 : (mat == 1) ? w1 : (mat == 2) ? w2 : w3;
        unsigned hh[4];
        #pragma unroll
        for (int j = 0; j < 4; j++)
            hh[j] = packh(W[(size_t)(k8 * 8 + 2 * j) * Dd + n],
                          W[(size_t)(k8 * 8 + 2 * j + 1) * Dd + n]);
        *(uint4*)&g_w2h[((size_t)mat * 512 + n) * 256 + k8 * 4] =
            make_uint4(hh[0], hh[1], hh[2], hh[3]);
    }
}

__global__ __launch_bounds__(256) void conv_attn(const float* __restrict__ A)
{
    const int gid = blockIdx.x * 256 + threadIdx.x;
    const int row = gid >> 7, col = (gid & 127) << 2;
    float4 v = *(const float4*)(A + (size_t)row * Dd + col);
    unsigned h0, l0, h1, l1;
    split2h(v.x, v.y, h0, l0);
    split2h(v.z, v.w, h1, l1);
    *(uint2*)&g_a2h[(size_t)row * 256 + (col >> 1)] = make_uint2(h0, h1);
    *(uint2*)&g_a2l[(size_t)row * 256 + (col >> 1)] = make_uint2(l0, l1);
}

// ---------------- pipelined 2-term fp16 GEMM ----------------
// 128m x 64n tile, 16 chunks of k=32, 2-stage cp.async pipeline.
#define B_AH 0u          // [2][128][20w]
#define B_AL 20480u
#define B_BH 40960u      // [2][64][20w]
#define GS_TOT 51200

__global__ __launch_bounds__(256) void gemm5(
    const float* __restrict__ biasK, float* __restrict__ outK,
    const float* __restrict__ biasV, float* __restrict__ outV,
    const float* __restrict__ biasQ, float* __restrict__ outQ,
    int qkvMode)
{
    const int m0 = blockIdx.y << 7, n0 = blockIdx.x << 6;
    int widx, bt, tok_off, mode, Lout, rnd;
    const float* bias; float* Out;
    if (qkvMode) {
        const int z = blockIdx.z;
        if (z == 2 && blockIdx.y >= 32) return;
        if (z == 0)      { widx = 1; bias = biasK; Out = outK; bt = LS;  tok_off = 0;         Lout = LK; rnd = 0; }
        else if (z == 1) { widx = 2; bias = biasV; Out = outV; bt = LS;  tok_off = 0;         Lout = LK; rnd = 1; }
        else             { widx = 0; bias = biasQ; Out = outQ; bt = LSO; tok_off = LS - LSO;  Lout = LQ; rnd = 0; }
        mode = 1;
    } else {
        widx = 3; bias = biasK; Out = outK; bt = LQ; tok_off = 0; Lout = 0; rnd = 0; mode = 0;
    }

    extern __shared__ __align__(16) char smem[];
    const uint32_t sb = smem_u32(smem);
    const int tid = threadIdx.x;
    const int lane = tid & 31, warp = tid >> 5;
    const int wm = warp >> 1, wn = warp & 1;
    const int g = lane >> 2, tg = lane & 3;

    const int arow0 = qkvMode ? ((m0 / bt) * LS + tok_off + (m0 % bt)) : m0;
    const char* aH = (const char*)(qkvMode ? g_x2h : g_a2h) + (size_t)arow0 * 1024;
    const char* aL = (const char*)(qkvMode ? g_x2l : g_a2l) + (size_t)arow0 * 1024;
    const char* bH = (const char*)g_w2h + ((size_t)widx * 512 + n0) * 1024;

    const int arow = tid >> 1;
    const int ach0 = (tid & 1) * 2;
    const int brow = tid >> 2;
    const int bch  = tid & 3;

    float acc[2][4][4];
    #pragma unroll
    for (int a = 0; a < 2; a++)
        #pragma unroll
        for (int b = 0; b < 4; b++)
            #pragma unroll
            for (int c = 0; c < 4; c++) acc[a][b][c] = 0.f;

#define G_LOAD(c, st) { \
    const size_t ao = (size_t)arow * 1024 + (size_t)(c) * 64; \
    cp16(sb + B_AH + (st) * 10240u + arow * 80 + (ach0 + 0) * 16, aH + ao + (ach0 + 0) * 16); \
    cp16(sb + B_AH + (st) * 10240u + arow * 80 + (ach0 + 1) * 16, aH + ao + (ach0 + 1) * 16); \
    cp16(sb + B_AL + (st) * 10240u + arow * 80 + (ach0 + 0) * 16, aL + ao + (ach0 + 0) * 16); \
    cp16(sb + B_AL + (st) * 10240u + arow * 80 + (ach0 + 1) * 16, aL + ao + (ach0 + 1) * 16); \
    cp16(sb + B_BH + (st) * 5120u + brow * 80 + bch * 16, \
         bH + (size_t)brow * 1024 + (size_t)(c) * 64 + bch * 16); \
    cp_commit(); }

    G_LOAD(0, 0);

    for (int c = 0; c < 16; c++) {
        const int nc = (c + 1 < 16) ? c + 1 : 15;
        G_LOAD(nc, (c + 1) & 1);
        cp_wait1();
        __syncthreads();

        const unsigned* A_h = (const unsigned*)(smem + B_AH + (c & 1) * 10240u);
        const unsigned* A_l = (const unsigned*)(smem + B_AL + (c & 1) * 10240u);
        const unsigned* Bh_ = (const unsigned*)(smem + B_BH + (c & 1) * 5120u);

        #pragma unroll
        for (int s2 = 0; s2 < 2; s2++) {
            const int k2o = s2 * 8;
            unsigned ah[2][4], al[2][4], bh[4][2];
            #pragma unroll
            for (int mt = 0; mt < 2; mt++) {
                const int mr = wm * 32 + mt * 16;
                ah[mt][0] = A_h[(mr + g) * 20 + k2o + tg];
                ah[mt][1] = A_h[(mr + g + 8) * 20 + k2o + tg];
                ah[mt][2] = A_h[(mr + g) * 20 + k2o + tg + 4];
                ah[mt][3] = A_h[(mr + g + 8) * 20 + k2o + tg + 4];
                al[mt][0] = A_l[(mr + g) * 20 + k2o + tg];
                al[mt][1] = A_l[(mr + g + 8) * 20 + k2o + tg];
                al[mt][2] = A_l[(mr + g) * 20 + k2o + tg + 4];
                al[mt][3] = A_l[(mr + g + 8) * 20 + k2o + tg + 4];
            }
            #pragma unroll
            for (int nt = 0; nt < 4; nt++) {
                const int nc2 = wn * 32 + nt * 8 + g;
                bh[nt][0] = Bh_[nc2 * 20 + k2o + tg];
                bh[nt][1] = Bh_[nc2 * 20 + k2o + tg + 4];
            }
            #pragma unroll
            for (int mt = 0; mt < 2; mt++)
                #pragma unroll
                for (int nt = 0; nt < 4; nt++) {
                    mma16h(acc[mt][nt], ah[mt], bh[nt]);
                    mma16h(acc[mt][nt], al[mt], bh[nt]);
                }
        }
        __syncthreads();
    }

    #pragma unroll
    for (int mt = 0; mt < 2; mt++)
        #pragma unroll
        for (int j2 = 0; j2 < 2; j2++) {
            const int m = m0 + wm * 32 + mt * 16 + g + j2 * 8;
            const int b = m / bt, t = m % bt;
            #pragma unroll
            for (int nt = 0; nt < 4; nt++) {
                const int n = n0 + wn * 32 + nt * 8 + 2 * tg;
                float c0 = acc[mt][nt][j2 * 2 + 0] + bias[n];
                float c1 = acc[mt][nt][j2 * 2 + 1] + bias[n + 1];
                if (rnd) {
                    c0 = __uint_as_float(f2tf(c0));
                    c1 = __uint_as_float(f2tf(c1));
                }
                if (mode == 0) {
                    *(float2*)&Out[(size_t)m * Dd + n] = make_float2(c0, c1);
                } else {
                    const int h = n >> 6, dd = n & 63;
                    *(float2*)&Out[(((size_t)b * Hh + h) * Lout + t) * HD + dd] =
                        make_float2(c0, c1);
                }
            }
        }
}

// ---------------- per-token projections (fused 3-in-1) ----------------
__global__ __launch_bounds__(256) void ns_proj(
    const float* __restrict__ x,
    const float* __restrict__ nw0, const float* __restrict__ nb0, float* __restrict__ o0,
    const float* __restrict__ nw1, const float* __restrict__ nb1, float* __restrict__ o1,
    const float* __restrict__ nw2, const float* __restrict__ nb2, float* __restrict__ o2)
{
    const int z = blockIdx.z;
    const float* nw = (z == 0) ? nw0 : (z == 1) ? nw1 : nw2;
    const float* nb = (z == 0) ? nb0 : (z == 1) ? nb1 : nb2;
    float* Out      = (z == 0) ? o0  : (z == 1) ? o1  : o2;
    const int Lout        = (z == 0) ? LQ  : LK;
    const int out_tok_off = (z == 0) ? LSO : LS;

    const int n = blockIdx.x, tid = threadIdx.x;
    const int cgrp = tid & 31, kh = tid >> 5, kbeg = kh * 64;
    const int colb = blockIdx.y * 128;

    __shared__ float xs[8][512];
    __shared__ float red[8][8][128];

    for (int i = tid; i < 8 * 512; i += 256) {
        const int b = i >> 9, k = i & 511;
        xs[b][k] = x[((size_t)b * LL + LS + n) * Dd + k];
    }
    __syncthreads();

    const float4* wp4 = (const float4*)(nw + (size_t)n * Dd * Dd) + (colb >> 2) + cgrp;
    float acc[8][4];
    #pragma unroll
    for (int b = 0; b < 8; b++)
        #pragma unroll
        for (int j = 0; j < 4; j++) acc[b][j] = 0.f;

    for (int k = 0; k < 64; k += 4) {
        float4 w[4];
        #pragma unroll
        for (int u = 0; u < 4; u++) w[u] = wp4[(size_t)(kbeg + k + u) * 128];
        #pragma unroll
        for (int u = 0; u < 4; u++)
            #pragma unroll
            for (int b = 0; b < 8; b++) {
                const float s = xs[b][kbeg + k + u];
                acc[b][0] += s * w[u].x; acc[b][1] += s * w[u].y;
                acc[b][2] += s * w[u].z; acc[b][3] += s * w[u].w;
            }
    }
    #pragma unroll
    for (int b = 0; b < 8; b++)
        *(float4*)&red[kh][b][cgrp * 4] = make_float4(acc[b][0], acc[b][1], acc[b][2], acc[b][3]);
    __syncthreads();

    for (int i = tid; i < 8 * 128; i += 256) {
        const int b = i >> 7, c = i & 127;
        float s = 0.f;
        #pragma unroll
        for (int k8 = 0; k8 < 8; k8++) s += red[k8][b][c];
        const int col = colb + c, h = col >> 6, dd = col & 63;
        float v = s + nb[(size_t)n * Dd + col];
        if (z == 2) v = __uint_as_float(f2tf(v));   // V pre-rounded tf32-rn
        Out[(((size_t)b * Hh + h) * Lout + out_tok_off + n) * HD + dd] = v;
    }
}

// ---------------- flash attention: Q-in-regs, double-buffered K/V ----------------
#define A_KST 68
#define A_VST 72
#define A_VOFF (2 * 64 * A_KST)
#define A_POFF (A_VOFF + 2 * 64 * A_VST)
#define ATTN_SMEM (A_POFF * 4 + 2 * 64 * 4)

__global__ __launch_bounds__(128) void attn_tc(
    const float* __restrict__ Q, const float* __restrict__ K,
    const float* __restrict__ V, const int* __restrict__ pad_mask,
    float* __restrict__ Outp)
{
    extern __shared__ __align__(16) float smf[];
    float* Ks = smf;
    float* Vs = smf + A_VOFF;
    int*   padi = (int*)(smf + A_POFF);

    const int tid = threadIdx.x, lane = tid & 31, warp = tid >> 5;
    const int g = lane >> 2, tg = lane & 3;
    const int bh = blockIdx.y, b = bh >> 3, h = bh & 7;
    const int q0 = blockIdx.x << 6;
    const int mr = warp * 16;

    const float* Qp = Q + ((size_t)bh * LQ + q0) * HD;
    const float* Kp = K + (size_t)bh * LK * HD;
    const float* Vp = V + (size_t)bh * LK * HD;
    const uint32_t ks_u = smem_u32(Ks);
    const uint32_t vs_u = smem_u32(Vs);
    const uint32_t pd_u = smem_u32(padi);

    unsigned aq[8][4];
    #pragma unroll
    for (int ks = 0; ks < 8; ks++) {
        aq[ks][0] = f2tf(Qp[(size_t)(mr + g) * HD + ks * 8 + tg] * 0.125f);
        aq[ks][1] = f2tf(Qp[(size_t)(mr + g + 8) * HD + ks * 8 + tg] * 0.125f);
        aq[ks][2] = f2tf(Qp[(size_t)(mr + g) * HD + ks * 8 + tg + 4] * 0.125f);
        aq[ks][3] = f2tf(Qp[(size_t)(mr + g + 8) * HD + ks * 8 + tg + 4] * 0.125f);
    }

    float o[8][4];
    #pragma unroll
    for (int nt = 0; nt < 8; nt++)
        #pragma unroll
        for (int j = 0; j < 4; j++) o[nt][j] = 0.f;
    float m_run[2] = {-1e30f, -1e30f};
    float l_run[2] = {0.f, 0.f};

    const int row0 = q0 + mr + g;
    const int ntiles = min(LK >> 6, ((q0 + 63 + DELTA) >> 6) + 1);

#define A_LOAD(t, st) { \
    _Pragma("unroll") \
    for (int i = 0; i < 8; i++) { \
        const int idx = i * 128 + tid; \
        const int r = idx >> 4, ch = idx & 15; \
        cp16(ks_u + (st) * 17408u + r * 272u + ch * 16u, \
             (const char*)Kp + ((size_t)((t) * 64 + r)) * 256 + ch * 16); \
        cp16(vs_u + (st) * 18432u + r * 288u + ch * 16u, \
             (const char*)Vp + ((size_t)((t) * 64 + r)) * 256 + ch * 16); \
    } \
    if ((t) * 64 < LS) { \
        if (tid < 16) \
            cp16(pd_u + (st) * 256u + tid * 16u, \
                 (const char*)(pad_mask + (size_t)b * LS + (t) * 64) + tid * 16); \
    } else { \
        if (tid < 64) padi[(st) * 64 + tid] = 1; \
    } \
    cp_commit(); }

    A_LOAD(0, 0);

    for (int kt = 0; kt < ntiles; kt++) {
        const int nxt = (kt + 1 < ntiles) ? kt + 1 : ntiles - 1;
        A_LOAD(nxt, (kt + 1) & 1);
        cp_wait1();
        __syncthreads();

        const float* Kc = Ks + (kt & 1) * 64 * A_KST;
        const float* Vc = Vs + (kt & 1) * 64 * A_VST;
        const int*   pc = padi + (kt & 1) * 64;
        const int k0 = kt << 6;

        float sc[8][4];
        #pragma unroll
        for (int nt = 0; nt < 8; nt++)
            #pragma unroll
            for (int j = 0; j < 4; j++) sc[nt][j] = 0.f;

        #pragma unroll
        for (int ks = 0; ks < 8; ks++)
            #pragma unroll
            for (int nt = 0; nt < 8; nt++) {
                unsigned bb[2];
                bb[0] = __float_as_uint(Kc[(nt * 8 + g) * A_KST + ks * 8 + tg]);
                bb[1] = __float_as_uint(Kc[(nt * 8 + g) * A_KST + ks * 8 + tg + 4]);
                mma8(sc[nt], aq[ks], bb);
            }

        float mx0 = -1e30f, mx1 = -1e30f;
        #pragma unroll
        for (int nt = 0; nt < 8; nt++) {
            const int cb = k0 + nt * 8 + 2 * tg;
            const int p0 = pc[nt * 8 + 2 * tg];
            const int p1 = pc[nt * 8 + 2 * tg + 1];
            if (cb     > row0 + DELTA     || !p0) sc[nt][0] = -1e9f;
            if (cb + 1 > row0 + DELTA     || !p1) sc[nt][1] = -1e9f;
            if (cb     > row0 + 8 + DELTA || !p0) sc[nt][2] = -1e9f;
            if (cb + 1 > row0 + 8 + DELTA || !p1) sc[nt][3] = -1e9f;
            mx0 = fmaxf(mx0, fmaxf(sc[nt][0], sc[nt][1]));
            mx1 = fmaxf(mx1, fmaxf(sc[nt][2], sc[nt][3]));
        }
        mx0 = fmaxf(mx0, __shfl_xor_sync(0xffffffffu, mx0, 1));
        mx0 = fmaxf(mx0, __shfl_xor_sync(0xffffffffu, mx0, 2));
        mx1 = fmaxf(mx1, __shfl_xor_sync(0xffffffffu, mx1, 1));
        mx1 = fmaxf(mx1, __shfl_xor_sync(0xffffffffu, mx1, 2));

        const float mn0 = fmaxf(m_run[0], mx0), mn1 = fmaxf(m_run[1], mx1);
        const float cr0 = __expf(m_run[0] - mn0), cr1 = __expf(m_run[1] - mn1);

        float ls0 = 0.f, ls1 = 0.f;
        #pragma unroll
        for (int nt = 0; nt < 8; nt++) {
            sc[nt][0] = __expf(sc[nt][0] - mn0); ls0 += sc[nt][0];
            sc[nt][1] = __expf(sc[nt][1] - mn0); ls0 += sc[nt][1];
            sc[nt][2] = __expf(sc[nt][2] - mn1); ls1 += sc[nt][2];
            sc[nt][3] = __expf(sc[nt][3] - mn1); ls1 += sc[nt][3];
        }
        ls0 += __shfl_xor_sync(0xffffffffu, ls0, 1);
        ls0 += __shfl_xor_sync(0xffffffffu, ls0, 2);
        ls1 += __shfl_xor_sync(0xffffffffu, ls1, 1);
        ls1 += __shfl_xor_sync(0xffffffffu, ls1, 2);

        l_run[0] = l_run[0] * cr0 + ls0;
        l_run[1] = l_run[1] * cr1 + ls1;
        m_run[0] = mn0; m_run[1] = mn1;

        #pragma unroll
        for (int nt = 0; nt < 8; nt++) {
            o[nt][0] *= cr0; o[nt][1] *= cr0;
            o[nt][2] *= cr1; o[nt][3] *= cr1;
        }

        #pragma unroll
        for (int ks = 0; ks < 8; ks++) {
            const int s0 = (lane & ~3) | (tg >> 1);
            const int s1 = s0 + 2;
            unsigned a[4];
            {
                float e0 = __shfl_sync(0xffffffffu, sc[ks][0], s0);
                float e1 = __shfl_sync(0xffffffffu, sc[ks][1], s0);
                a[0] = f2tf((tg & 1) ? e1 : e0);
                float e2 = __shfl_sync(0xffffffffu, sc[ks][2], s0);
                float e3 = __shfl_sync(0xffffffffu, sc[ks][3], s0);
                a[1] = f2tf((tg & 1) ? e3 : e2);
                float f0 = __shfl_sync(0xffffffffu, sc[ks][0], s1);
                float f1 = __shfl_sync(0xffffffffu, sc[ks][1], s1);
                a[2] = f2tf((tg & 1) ? f1 : f0);
                float f2v = __shfl_sync(0xffffffffu, sc[ks][2], s1);
                float f3v = __shfl_sync(0xffffffffu, sc[ks][3], s1);
                a[3] = f2tf((tg & 1) ? f3v : f2v);
            }
            #pragma unroll
            for (int nt = 0; nt < 8; nt++) {
                unsigned bb[2];
                bb[0] = __float_as_uint(Vc[(ks * 8 + tg) * A_VST + nt * 8 + g]);
                bb[1] = __float_as_uint(Vc[(ks * 8 + tg + 4) * A_VST + nt * 8 + g]);
                mma8(o[nt], a, bb);
            }
        }
        __syncthreads();
    }

    const float inv0 = (l_run[0] > 0.f) ? 1.f / l_run[0] : 0.f;
    const float inv1 = (l_run[1] > 0.f) ? 1.f / l_run[1] : 0.f;
    float* op0 = Outp + ((size_t)b * LQ + row0) * Dd + h * HD;
    float* op1 = op0 + (size_t)8 * Dd;
    #pragma unroll
    for (int nt = 0; nt < 8; nt++) {
        const int dc = nt * 8 + 2 * tg;
        *(float2*)(op0 + dc) = make_float2(o[nt][0] * inv0, o[nt][1] * inv0);
        *(float2*)(op1 + dc) = make_float2(o[nt][2] * inv1, o[nt][3] * inv1);
    }
}

// ---------------------------------------------------------------------------
extern "C" void kernel_launch(void* const* d_in, const int* in_sizes, int n_in,
                              void* d_out, int out_size)
{
    const float* x        = (const float*)d_in[0];
    const int*   pad_mask = (const int*)  d_in[1];
    const float* wq_sw = (const float*)d_in[4];
    const float* wq_sb = (const float*)d_in[5];
    const float* wq_nw = (const float*)d_in[6];
    const float* wq_nb = (const float*)d_in[7];
    const float* wk_sw = (const float*)d_in[8];
    const float* wk_sb = (const float*)d_in[9];
    const float* wk_nw = (const float*)d_in[10];
    const float* wk_nb = (const float*)d_in[11];
    const float* wv_sw = (const float*)d_in[12];
    const float* wv_sb = (const float*)d_in[13];
    const float* wv_nw = (const float*)d_in[14];
    const float* wv_nb = (const float*)d_in[15];
    const float* out_w = (const float*)d_in[16];
    const float* out_b = (const float*)d_in[17];
    float* out = (float*)d_out;

    float *pQ, *pK, *pV, *pA;
    cudaGetSymbolAddress((void**)&pQ, g_Q);
    cudaGetSymbolAddress((void**)&pK, g_K);
    cudaGetSymbolAddress((void**)&pV, g_V);
    cudaGetSymbolAddress((void**)&pA, g_attn);

    cudaFuncSetAttribute(gemm5, cudaFuncAttributeMaxDynamicSharedMemorySize, GS_TOT);
    cudaFuncSetAttribute(attn_tc, cudaFuncAttributeMaxDynamicSharedMemorySize, ATTN_SMEM);

    // 1: pre-split x (fp16 hi/lo) + 4 weight matrices (fp16 hi)
    conv_in<<<8704, 256>>>(x, wq_sw, wk_sw, wv_sw, out_w);
    // 2: fused Q+K+V projections (2-term fp16 MMA; V epilogue rounds tf32-rn)
    gemm5<<<dim3(8, 128, 3), 256, GS_TOT>>>(wk_sb, pK, wv_sb, pV, wq_sb, pQ, 1);
    // 3: per-token projections (fused; V branch rounds)
    ns_proj<<<dim3(64, 4, 3), 256>>>(x, wq_nw, wq_nb, pQ, wk_nw, wk_nb, pK,
                                     wv_nw, wv_nb, pV);
    // 4: attention  <-- profiled slot
    attn_tc<<<dim3(LQ / 64, Bc * Hh), 128, ATTN_SMEM>>>(pQ, pK, pV, pad_mask, pA);
    // 5: split attn output
    conv_attn<<<2304, 256>>>(pA);
    // 6: output projection
    gemm5<<<dim3(8, 36, 1), 256, GS_TOT>>>(out_b, out, 0, 0, 0, 0, 0);
}